// round 2
// baseline (speedup 1.0000x reference)
#include <cuda_runtime.h>

// Problem constants
#define BB 8192   // batch
#define DD 1024   // dim
#define KK 4096   // codebook size
#define LL 8      // max word length

// GEMM tiling
#define BM 64
#define BN 128
#define BK 16
#define TM 8
#define TN 4
#define NTHR 256  // (BM/TM)*(BN/TN) = 8*32

// Persistent scratch (static __device__ arrays: allowed; no runtime alloc)
__device__ float         g_resid[BB * DD];        // 32 MB residual buffer
__device__ unsigned char g_active[BB];
__device__ float         g_idx_scratch[BB * LL];  // fallback index buffer

// One fused step:
//   scores = residual @ codebook^T  (fp32, fused argmax, never materialized)
//   norm check -> active update -> write index -> residual -= decay*codebook[idx]
__global__ __launch_bounds__(NTHR) void lex_step(
    const float* __restrict__ codebook,
    float* __restrict__ idx_out,
    float decay, int step)
{
    __shared__ float As[BK][BM];    // residual tile, transposed [k][m]
    __shared__ float Bs[BK][BN];    // codebook tile, transposed [k][n]
    __shared__ float sVal[BM][32];
    __shared__ int   sIdx[BM][32];
    __shared__ int   sWin[BM];

    const int tid = threadIdx.x;
    const int m0  = blockIdx.x * BM;
    const int tn  = tid & 31;   // 0..31  (column group of TN)
    const int tm  = tid >> 5;   // 0..7   (row group of TM)

    float bestVal[TM];
    int   bestIdx[TM];
#pragma unroll
    for (int i = 0; i < TM; i++) { bestVal[i] = -3.402823466e38f; bestIdx[i] = 0; }

    // Global-load index mapping (float4 granularity)
    const int aRow = tid >> 2;          // 0..63
    const int aC4  = tid & 3;           // 0..3
    const float* aPtr = g_resid + (size_t)(m0 + aRow) * DD + aC4 * 4;
    const int bRow0 = tid >> 2;         // 0..63
    const int bRow1 = bRow0 + 64;       // 64..127
    const int bC4   = tid & 3;

    for (int n0 = 0; n0 < KK; n0 += BN) {
        float acc[TM][TN];
#pragma unroll
        for (int i = 0; i < TM; i++)
#pragma unroll
            for (int j = 0; j < TN; j++) acc[i][j] = 0.0f;

        const float* b0p = codebook + (size_t)(n0 + bRow0) * DD + bC4 * 4;
        const float* b1p = codebook + (size_t)(n0 + bRow1) * DD + bC4 * 4;

        // prefetch k-tile 0
        float4 ra  = *(const float4*)(aPtr);
        float4 rb0 = __ldg((const float4*)(b0p));
        float4 rb1 = __ldg((const float4*)(b1p));

        for (int k0 = 0; k0 < DD; k0 += BK) {
            // commit prefetched regs to smem (transposed)
            As[aC4*4+0][aRow] = ra.x;  As[aC4*4+1][aRow] = ra.y;
            As[aC4*4+2][aRow] = ra.z;  As[aC4*4+3][aRow] = ra.w;
            Bs[bC4*4+0][bRow0] = rb0.x; Bs[bC4*4+1][bRow0] = rb0.y;
            Bs[bC4*4+2][bRow0] = rb0.z; Bs[bC4*4+3][bRow0] = rb0.w;
            Bs[bC4*4+0][bRow1] = rb1.x; Bs[bC4*4+1][bRow1] = rb1.y;
            Bs[bC4*4+2][bRow1] = rb1.z; Bs[bC4*4+3][bRow1] = rb1.w;
            __syncthreads();

            // prefetch next k-tile (issued before the FFMA burst)
            const int kn = k0 + BK;
            float4 na = ra, nb0 = rb0, nb1 = rb1;
            if (kn < DD) {
                na  = *(const float4*)(aPtr + kn);
                nb0 = __ldg((const float4*)(b0p + kn));
                nb1 = __ldg((const float4*)(b1p + kn));
            }

#pragma unroll
            for (int k = 0; k < BK; k++) {
                float4 a0 = *(const float4*)&As[k][tm * TM];
                float4 a1 = *(const float4*)&As[k][tm * TM + 4];
                float4 b0 = *(const float4*)&Bs[k][tn * TN];
                float av[TM] = {a0.x, a0.y, a0.z, a0.w, a1.x, a1.y, a1.z, a1.w};
                float bv[TN] = {b0.x, b0.y, b0.z, b0.w};
#pragma unroll
                for (int i = 0; i < TM; i++)
#pragma unroll
                    for (int j = 0; j < TN; j++)
                        acc[i][j] = fmaf(av[i], bv[j], acc[i][j]);
            }
            __syncthreads();
            ra = na; rb0 = nb0; rb1 = nb1;
        }

        // fold tile scores into running per-row argmax.
        // within a thread, columns are visited in ascending global index;
        // strict '>' keeps the FIRST max (jnp.argmax tie rule)
#pragma unroll
        for (int i = 0; i < TM; i++) {
#pragma unroll
            for (int j = 0; j < TN; j++) {
                int idx = n0 + tn * TN + j;
                if (acc[i][j] > bestVal[i]) { bestVal[i] = acc[i][j]; bestIdx[i] = idx; }
            }
        }
    }

    // cross-thread argmax reduction (32 partials per row)
#pragma unroll
    for (int i = 0; i < TM; i++) {
        sVal[tm * TM + i][tn] = bestVal[i];
        sIdx[tm * TM + i][tn] = bestIdx[i];
    }
    __syncthreads();
    if (tid < BM) {
        float bv = sVal[tid][0]; int bi = sIdx[tid][0];
#pragma unroll 4
        for (int t = 1; t < 32; t++) {
            float v = sVal[tid][t]; int id = sIdx[tid][t];
            if (v > bv || (v == bv && id < bi)) { bv = v; bi = id; }
        }
        sWin[tid] = bi;
    }
    __syncthreads();

    // norm check (on PRE-update residual), active update, index emit, residual update
    const int warp = tid >> 5, lane = tid & 31;
    for (int r = warp; r < BM; r += (NTHR / 32)) {
        const int row = m0 + r;
        float* rp = g_resid + (size_t)row * DD;

        float s = 0.0f;
#pragma unroll
        for (int d4 = lane; d4 < DD / 4; d4 += 32) {
            float4 v = *(const float4*)(rp + d4 * 4);
            s += v.x * v.x + v.y * v.y + v.z * v.z + v.w * v.w;
        }
#pragma unroll
        for (int off = 16; off; off >>= 1) s += __shfl_xor_sync(0xffffffffu, s, off);

        const int idx = sWin[r];
        int act = 0;
        if (lane == 0) {
            act = (int)g_active[row] && (s >= 1e-6f);   // norm >= 1e-3
            g_active[row] = (unsigned char)act;
            idx_out[(size_t)row * LL + step] = act ? (float)idx : -1.0f;
        }
        act = __shfl_sync(0xffffffffu, act, 0);
        const float dm = act ? decay : 0.0f;

        const float* cp = codebook + (size_t)idx * DD;
#pragma unroll
        for (int d4 = lane; d4 < DD / 4; d4 += 32) {
            float4 v = *(const float4*)(rp + d4 * 4);
            float4 c = *(const float4*)(cp + d4 * 4);
            v.x -= dm * c.x; v.y -= dm * c.y; v.z -= dm * c.z; v.w -= dm * c.w;
            *(float4*)(rp + d4 * 4) = v;
        }
    }
}

// fallback: if the harness output is indices-only it would be int32
__global__ void f2i_kernel(const float* __restrict__ src, int* __restrict__ dst, int n) {
    int i = blockIdx.x * blockDim.x + threadIdx.x;
    if (i < n) dst[i] = (int)src[i];
}

extern "C" void kernel_launch(void* const* d_in, const int* in_sizes, int n_in,
                              void* d_out, int out_size)
{
    const float* targets  = (const float*)d_in[0];
    const float* codebook = (const float*)d_in[1];

    void *residPtr = nullptr, *activePtr = nullptr, *scrPtr = nullptr;
    cudaGetSymbolAddress(&residPtr, g_resid);
    cudaGetSymbolAddress(&activePtr, g_active);
    cudaGetSymbolAddress(&scrPtr, g_idx_scratch);

    const int IDX_N = BB * LL;        // 65536
    const int RES_N = BB * DD;        // 8388608
    float* out = (float*)d_out;

    // 0.9^s, s = 0..7 (precomputed; no host libm in the capture path)
    static const float kDecay[LL] = {
        1.0f, 0.9f, 0.81f, 0.729f, 0.6561f, 0.59049f, 0.531441f, 0.4782969f
    };

    // Expected layout: [indices (B*L) | residual (B*D)] as float32.
    float* idx_out;
    const bool full_layout = (out_size >= IDX_N + RES_N);
    if (full_layout)              idx_out = out;
    else                          idx_out = (float*)scrPtr;

    cudaMemcpyAsync(residPtr, targets, (size_t)RES_N * sizeof(float),
                    cudaMemcpyDeviceToDevice, 0);
    cudaMemsetAsync(activePtr, 1, BB, 0);

    for (int s = 0; s < LL; s++) {
        lex_step<<<BB / BM, NTHR>>>(codebook, idx_out, kDecay[s], s);
    }

    if (full_layout) {
        cudaMemcpyAsync(out + IDX_N, residPtr, (size_t)RES_N * sizeof(float),
                        cudaMemcpyDeviceToDevice, 0);
    } else if (out_size == RES_N) {
        // residual-only output
        cudaMemcpyAsync(out, residPtr, (size_t)RES_N * sizeof(float),
                        cudaMemcpyDeviceToDevice, 0);
    } else if (out_size == IDX_N) {
        // indices-only output -> int32
        f2i_kernel<<<(IDX_N + 255) / 256, 256>>>((const float*)scrPtr, (int*)d_out, IDX_N);
    } else if (out_size > 0) {
        // unknown smaller layout: emit as many float indices as fit
        int n = out_size < IDX_N ? out_size : IDX_N;
        cudaMemcpyAsync(out, scrPtr, (size_t)n * sizeof(float),
                        cudaMemcpyDeviceToDevice, 0);
    }
}

// round 3
// speedup vs baseline: 8.1789x; 8.1789x over previous
#include <cuda_runtime.h>

#define BB 8192   // batch
#define DD 1024   // dim
#define KK 4096   // codebook size
#define LL 8      // max word length

// ---- persistent scratch (static __device__: allowed; no runtime alloc) ----
__device__ float g_scores[BB * KK];       // 134 MB score matrix
__device__ float g_gram[KK * KK];         //  67 MB codebook Gram matrix
__device__ float g_norm2[BB];             // running ||residual||^2
__device__ float g_winval[BB];            // last argmax winning score
__device__ float g_idx_scratch[BB * LL];  // fallback index buffer

__constant__ float c_decay[LL] = {
    1.0f, 0.9f, 0.81f, 0.729f, 0.6561f, 0.59049f, 0.531441f, 0.4782969f
};

// ============================================================
// NT SGEMM: C[M,4096] = A[M,1024] @ B[4096,1024]^T
// 128x128 tile, BK=8, 256 thr, 8x8 per thread, reg prefetch.
// sym=1: A==B (Gram). Compute upper-triangle block pairs only,
// mirror-write the transpose tile.
// ============================================================
#define GBM 128
#define GBN 128
#define GBK 8

__global__ __launch_bounds__(256, 2) void gemm_nt(
    const float* __restrict__ A, const float* __restrict__ B,
    float* __restrict__ C, int sym)
{
    __shared__ float As[GBK][GBM];
    __shared__ float Bs[GBK][GBN];

    const int bj = blockIdx.x, bi = blockIdx.y;
    if (sym && bi > bj) return;

    const int tid  = threadIdx.x;
    const int lRow = tid >> 1;           // 0..127
    const int lK   = (tid & 1) * 4;      // 0 or 4
    const float* ap = A + (size_t)(bi * GBM + lRow) * DD + lK;
    const float* bp = B + (size_t)(bj * GBN + lRow) * DD + lK;

    const int tx = tid & 15;             // col group (8 cols)
    const int ty = tid >> 4;             // row group (8 rows)

    float acc[8][8];
#pragma unroll
    for (int i = 0; i < 8; i++)
#pragma unroll
        for (int j = 0; j < 8; j++) acc[i][j] = 0.0f;

    float4 ra = *(const float4*)ap;
    float4 rb = *(const float4*)bp;

    for (int k0 = 0; k0 < DD; k0 += GBK) {
        As[lK+0][lRow] = ra.x; As[lK+1][lRow] = ra.y;
        As[lK+2][lRow] = ra.z; As[lK+3][lRow] = ra.w;
        Bs[lK+0][lRow] = rb.x; Bs[lK+1][lRow] = rb.y;
        Bs[lK+2][lRow] = rb.z; Bs[lK+3][lRow] = rb.w;
        __syncthreads();

        if (k0 + GBK < DD) {
            ra = *(const float4*)(ap + k0 + GBK);
            rb = *(const float4*)(bp + k0 + GBK);
        }

#pragma unroll
        for (int k = 0; k < GBK; k++) {
            float4 a0 = *(const float4*)&As[k][ty * 8];
            float4 a1 = *(const float4*)&As[k][ty * 8 + 4];
            float4 b0 = *(const float4*)&Bs[k][tx * 8];
            float4 b1 = *(const float4*)&Bs[k][tx * 8 + 4];
            float av[8] = {a0.x, a0.y, a0.z, a0.w, a1.x, a1.y, a1.z, a1.w};
            float bv[8] = {b0.x, b0.y, b0.z, b0.w, b1.x, b1.y, b1.z, b1.w};
#pragma unroll
            for (int i = 0; i < 8; i++)
#pragma unroll
                for (int j = 0; j < 8; j++)
                    acc[i][j] = fmaf(av[i], bv[j], acc[i][j]);
        }
        __syncthreads();
    }

    const int r0 = bi * GBM + ty * 8;
    const int c0 = bj * GBN + tx * 8;
#pragma unroll
    for (int i = 0; i < 8; i++) {
        float4 w0 = {acc[i][0], acc[i][1], acc[i][2], acc[i][3]};
        float4 w1 = {acc[i][4], acc[i][5], acc[i][6], acc[i][7]};
        *(float4*)&C[(size_t)(r0 + i) * KK + c0]     = w0;
        *(float4*)&C[(size_t)(r0 + i) * KK + c0 + 4] = w1;
    }
    if (sym && bi != bj) {
#pragma unroll
        for (int i = 0; i < 8; i++)
#pragma unroll
            for (int j = 0; j < 8; j++)
                C[(size_t)(c0 + j) * KK + (r0 + i)] = acc[i][j];
    }
}

// ============================================================
// initial ||target||^2 per row (warp per row)
// ============================================================
__global__ __launch_bounds__(256) void norm0_kernel(const float* __restrict__ targets)
{
    const int warp = threadIdx.x >> 5, lane = threadIdx.x & 31;
    const int row = blockIdx.x * 8 + warp;
    const float* tp = targets + (size_t)row * DD;
    float s = 0.0f;
#pragma unroll
    for (int c4 = lane; c4 < DD / 4; c4 += 32) {
        float4 v = *(const float4*)(tp + c4 * 4);
        s += v.x * v.x + v.y * v.y + v.z * v.z + v.w * v.w;
    }
#pragma unroll
    for (int off = 16; off; off >>= 1) s += __shfl_xor_sync(0xffffffffu, s, off);
    if (lane == 0) g_norm2[row] = s;
}

// ============================================================
// one pursuit step on the score matrix (warp per row):
//   apply previous step's rank-1 score update (scores -= d*G[pidx,:]),
//   norm^2 recurrence, active check, argmax (first-max tie rule), emit.
// ============================================================
__global__ __launch_bounds__(256) void step_kernel(
    float* __restrict__ idx_out, int step, float dprev)
{
    const int warp = threadIdx.x >> 5, lane = threadIdx.x & 31;
    const int row = blockIdx.x * 8 + warp;
    float* sp = g_scores + (size_t)row * KK;

    int pidx = -1;
    if (step > 0) {
        float pv = idx_out[(size_t)row * LL + (step - 1)];
        if (pv >= 0.0f) pidx = (int)pv;
    }

    float bv = -3.402823466e38f; int bi = 0;

    if (pidx >= 0) {
        const float* gp = g_gram + (size_t)pidx * KK;
        for (int c4 = lane; c4 < KK / 4; c4 += 32) {
            float4 s = *(const float4*)(sp + c4 * 4);
            float4 g = *(const float4*)(gp + c4 * 4);
            s.x -= dprev * g.x; s.y -= dprev * g.y;
            s.z -= dprev * g.z; s.w -= dprev * g.w;
            *(float4*)(sp + c4 * 4) = s;
            const int c = c4 * 4;
            if (s.x > bv) { bv = s.x; bi = c;     }
            if (s.y > bv) { bv = s.y; bi = c + 1; }
            if (s.z > bv) { bv = s.z; bi = c + 2; }
            if (s.w > bv) { bv = s.w; bi = c + 3; }
        }
    } else {
        for (int c4 = lane; c4 < KK / 4; c4 += 32) {
            float4 s = *(const float4*)(sp + c4 * 4);
            const int c = c4 * 4;
            if (s.x > bv) { bv = s.x; bi = c;     }
            if (s.y > bv) { bv = s.y; bi = c + 1; }
            if (s.z > bv) { bv = s.z; bi = c + 2; }
            if (s.w > bv) { bv = s.w; bi = c + 3; }
        }
    }

    // warp argmax reduce; ties -> lowest index (jnp.argmax first-max rule)
#pragma unroll
    for (int off = 16; off; off >>= 1) {
        float ov = __shfl_xor_sync(0xffffffffu, bv, off);
        int   oi = __shfl_xor_sync(0xffffffffu, bi, off);
        if (ov > bv || (ov == bv && oi < bi)) { bv = ov; bi = oi; }
    }

    if (lane == 0) {
        const bool act_prev = (step == 0) ? true : (pidx >= 0);
        float norm2 = g_norm2[row];
        if (step > 0 && act_prev) {
            const float wv = g_winval[row];
            norm2 = norm2 - 2.0f * dprev * wv
                  + dprev * dprev * g_gram[(size_t)pidx * KK + pidx];
            g_norm2[row] = norm2;
        }
        const bool act = act_prev && (norm2 >= 1e-6f);   // norm >= 1e-3
        idx_out[(size_t)row * LL + step] = act ? (float)bi : -1.0f;
        g_winval[row] = bv;
    }
}

// ============================================================
// final residual: r = target - sum_s decay_s * C[idx_s]  (reference order)
// warp per row
// ============================================================
__global__ __launch_bounds__(256) void resid_kernel(
    const float* __restrict__ targets, const float* __restrict__ codebook,
    const float* __restrict__ idx_in, float* __restrict__ out)
{
    const int warp = threadIdx.x >> 5, lane = threadIdx.x & 31;
    const int row = blockIdx.x * 8 + warp;

    int   sidx[LL];
#pragma unroll
    for (int s = 0; s < LL; s++) {
        float pv = idx_in[(size_t)row * LL + s];
        sidx[s] = (pv >= 0.0f) ? (int)pv : -1;
    }

    const float* tp = targets + (size_t)row * DD;
    float* op = out + (size_t)row * DD;
#pragma unroll
    for (int c4 = lane; c4 < DD / 4; c4 += 32) {
        float4 v = *(const float4*)(tp + c4 * 4);
#pragma unroll
        for (int s = 0; s < LL; s++) {
            if (sidx[s] >= 0) {
                const float d = c_decay[s];
                float4 c = *(const float4*)(codebook + (size_t)sidx[s] * DD + c4 * 4);
                v.x -= d * c.x; v.y -= d * c.y; v.z -= d * c.z; v.w -= d * c.w;
            }
        }
        *(float4*)(op + c4 * 4) = v;
    }
}

__global__ void f2i_kernel(const float* __restrict__ src, int* __restrict__ dst, int n) {
    int i = blockIdx.x * blockDim.x + threadIdx.x;
    if (i < n) dst[i] = (int)src[i];
}

extern "C" void kernel_launch(void* const* d_in, const int* in_sizes, int n_in,
                              void* d_out, int out_size)
{
    const float* targets  = (const float*)d_in[0];
    const float* codebook = (const float*)d_in[1];

    void *scoresPtr = nullptr, *gramPtr = nullptr, *scrPtr = nullptr;
    cudaGetSymbolAddress(&scoresPtr, g_scores);
    cudaGetSymbolAddress(&gramPtr, g_gram);
    cudaGetSymbolAddress(&scrPtr, g_idx_scratch);

    const int IDX_N = BB * LL;        // 65536
    const int RES_N = BB * DD;        // 8388608
    float* out = (float*)d_out;

    static const float kDecay[LL] = {
        1.0f, 0.9f, 0.81f, 0.729f, 0.6561f, 0.59049f, 0.531441f, 0.4782969f
    };

    // Output layout: [indices (B*L) | residual (B*D)] fp32 (validated in R2).
    const bool full_layout = (out_size >= IDX_N + RES_N);
    float* idx_out = full_layout ? out : (float*)scrPtr;
    float* res_out = full_layout ? (out + IDX_N)
                   : (out_size == RES_N ? out : (float*)scoresPtr); // scratch sink

    // 1) scores0 = targets @ C^T   and   G = C @ C^T (symmetric)
    gemm_nt<<<dim3(KK / GBN, BB / GBM), 256>>>(targets, codebook, (float*)scoresPtr, 0);
    gemm_nt<<<dim3(KK / GBN, KK / GBM), 256>>>(codebook, codebook, (float*)gramPtr, 1);

    // 2) initial norms
    norm0_kernel<<<BB / 8, 256>>>(targets);

    // 3) 8 pursuit steps on the score matrix (rank-1 Gram updates)
    for (int s = 0; s < LL; s++) {
        step_kernel<<<BB / 8, 256>>>(idx_out, s, s > 0 ? kDecay[s - 1] : 0.0f);
    }

    // 4) reconstruct final residual in reference subtraction order
    resid_kernel<<<BB / 8, 256>>>(targets, codebook, idx_out, res_out);

    if (!full_layout && out_size == IDX_N) {
        f2i_kernel<<<(IDX_N + 255) / 256, 256>>>((const float*)scrPtr, (int*)d_out, IDX_N);
    }
}

// round 5
// speedup vs baseline: 11.1575x; 1.3642x over previous
#include <cuda_runtime.h>
#include <cuda_bf16.h>
#include <cstdint>

#define BB 8192   // batch
#define DD 1024   // dim
#define KK 4096   // codebook size
#define LL 8      // max word length
#define KSPLIT 6144  // 6 * 1024 (bf16 split pairings along K)

// ---------------- persistent scratch ----------------
__device__ float         g_scores[BB * KK];          // 134 MB
__device__ float         g_gram[KK * KK];            //  67 MB
__device__ float         g_norm2[BB];
__device__ float         g_idx_scratch[BB * LL];
__device__ __nv_bfloat16 g_Ta[(size_t)BB * KSPLIT];  // targets, A-variant
__device__ __nv_bfloat16 g_Ca[(size_t)KK * KSPLIT];  // codebook, A-variant
__device__ __nv_bfloat16 g_Cb[(size_t)KK * KSPLIT];  // codebook, B-variant

__constant__ float c_decay[LL] = {
    1.0f, 0.9f, 0.81f, 0.729f, 0.6561f, 0.59049f, 0.531441f, 0.4782969f
};

// ---------------- split conversion ----------------
// A-variant slots: [hi, mid, lo, hi, hi, mid]; B-variant: [hi, hi, hi, mid, lo, mid]
// => pairings hh + mh + lh + hm + hl + mm (drops ml, lm, ll ~ 2^-26)
__global__ __launch_bounds__(256) void split_targets(const float* __restrict__ src) {
    int i = blockIdx.x * 256 + threadIdx.x;             // over BB*DD
    float a = src[i];
    __nv_bfloat16 hi = __float2bfloat16(a);
    float r1 = a - __bfloat162float(hi);
    __nv_bfloat16 mid = __float2bfloat16(r1);
    __nv_bfloat16 lo  = __float2bfloat16(r1 - __bfloat162float(mid));
    size_t base = (size_t)(i >> 10) * KSPLIT + (i & 1023);
    g_Ta[base]        = hi;  g_Ta[base + 1024] = mid; g_Ta[base + 2048] = lo;
    g_Ta[base + 3072] = hi;  g_Ta[base + 4096] = hi;  g_Ta[base + 5120] = mid;
}
__global__ __launch_bounds__(256) void split_codebook(const float* __restrict__ src) {
    int i = blockIdx.x * 256 + threadIdx.x;             // over KK*DD
    float a = src[i];
    __nv_bfloat16 hi = __float2bfloat16(a);
    float r1 = a - __bfloat162float(hi);
    __nv_bfloat16 mid = __float2bfloat16(r1);
    __nv_bfloat16 lo  = __float2bfloat16(r1 - __bfloat162float(mid));
    size_t base = (size_t)(i >> 10) * KSPLIT + (i & 1023);
    g_Ca[base]        = hi;  g_Ca[base + 1024] = mid; g_Ca[base + 2048] = lo;
    g_Ca[base + 3072] = hi;  g_Ca[base + 4096] = hi;  g_Ca[base + 5120] = mid;
    g_Cb[base]        = hi;  g_Cb[base + 1024] = hi;  g_Cb[base + 2048] = hi;
    g_Cb[base + 3072] = mid; g_Cb[base + 4096] = lo;  g_Cb[base + 5120] = mid;
}

// ---------------- mma.sync bf16 GEMM: C[M,4096](+sym) = A'[M,6144] @ B'[4096,6144]^T ----
#define Bb 128          // BM
#define BN 128
#define BKT 32          // bf16 k per stage tile
#define NSTG 3
#define NKT (KSPLIT / BKT)     // 192
#define ASTRIDE 80             // bytes per smem row (32 halves + 8 pad)
#define STAGE_BYTES (2 * BB_ROWS * ASTRIDE)
#define BB_ROWS 128
#define B_OFF (BB_ROWS * ASTRIDE)       // 10240

__device__ __forceinline__ uint32_t smem_u32(const void* p) {
    uint32_t a;
    asm("{ .reg .u64 t; cvta.to.shared.u64 t, %1; cvt.u32.u64 %0, t; }" : "=r"(a) : "l"(p));
    return a;
}
__device__ __forceinline__ void cp16(uint32_t dst, const void* src) {
    asm volatile("cp.async.cg.shared.global [%0], [%1], 16;" :: "r"(dst), "l"(src) : "memory");
}
#define CP_COMMIT() asm volatile("cp.async.commit_group;" ::: "memory")
#define CP_WAIT(n)  asm volatile("cp.async.wait_group %0;" :: "n"(n) : "memory")

__device__ __forceinline__ void ldsm4(uint32_t& r0, uint32_t& r1, uint32_t& r2, uint32_t& r3,
                                      uint32_t addr) {
    asm volatile("ldmatrix.sync.aligned.m8n8.x4.shared.b16 {%0,%1,%2,%3}, [%4];"
                 : "=r"(r0), "=r"(r1), "=r"(r2), "=r"(r3) : "r"(addr));
}
__device__ __forceinline__ void mma16816(float* c, const uint32_t* a, const uint32_t* b) {
    asm volatile(
        "mma.sync.aligned.m16n8k16.row.col.f32.bf16.bf16.f32 "
        "{%0,%1,%2,%3}, {%4,%5,%6,%7}, {%8,%9}, {%0,%1,%2,%3};"
        : "+f"(c[0]), "+f"(c[1]), "+f"(c[2]), "+f"(c[3])
        : "r"(a[0]), "r"(a[1]), "r"(a[2]), "r"(a[3]), "r"(b[0]), "r"(b[1]));
}

extern __shared__ char dynsmem[];

__global__ __launch_bounds__(256, 2) void gemm_split(
    const __nv_bfloat16* __restrict__ A, const __nv_bfloat16* __restrict__ B,
    float* __restrict__ C, int sym)
{
    const int bj = blockIdx.x, bi = blockIdx.y;
    if (sym && bi > bj) return;

    const uint32_t sb = smem_u32(dynsmem);
    const int tid  = threadIdx.x;
    const int wid  = tid >> 5, lane = tid & 31;
    const int wm   = (wid & 1) * 64;     // warp M origin (2 warps in M)
    const int wn   = (wid >> 1) * 32;    // warp N origin (4 warps in N)
    const int m0   = bi * BB_ROWS;
    const int n0   = bj * BN;

    // per-thread load slots: 4 chunks of 16B per stage
    const int c0id = tid;                // +256,+512,+768

    auto load_stage = [&](int kt, int stg) {
        const uint32_t st = sb + stg * STAGE_BYTES;
        const size_t kofs = (size_t)kt * BKT;
#pragma unroll
        for (int q = 0; q < 4; q++) {
            int c = c0id + q * 256;      // 0..1023
            int isB = c >> 9;            // 0:A 1:B
            int cc = c & 511;
            int row = cc >> 2, seg = cc & 3;
            const __nv_bfloat16* src = (isB ? B + (size_t)(n0 + row) * KSPLIT
                                            : A + (size_t)(m0 + row) * KSPLIT)
                                       + kofs + seg * 8;
            uint32_t dst = st + isB * B_OFF + row * ASTRIDE + seg * 16;
            cp16(dst, src);
        }
    };

    float acc[4][4][4];                  // [mf][nf][reg]
#pragma unroll
    for (int i = 0; i < 4; i++)
#pragma unroll
        for (int j = 0; j < 4; j++)
#pragma unroll
            for (int r = 0; r < 4; r++) acc[i][j][r] = 0.0f;

    load_stage(0, 0); CP_COMMIT();
    load_stage(1, 1); CP_COMMIT();

    // ldmatrix address components (constant per thread)
    const uint32_t aRowSel = (lane & 15);            // m within 16
    const uint32_t aKByte  = (lane >> 4) * 16;       // k0 / k8 halves
    const uint32_t bRowSel = (lane & 7) + ((lane >> 4) << 3);  // n within 16
    const uint32_t bKByte  = ((lane >> 3) & 1) * 16;

    for (int kt = 0; kt < NKT; kt++) {
        CP_WAIT(1);
        __syncthreads();

        if (kt + 2 < NKT) load_stage(kt + 2, (kt + 2) % NSTG);
        CP_COMMIT();

        const uint32_t sa = sb + (kt % NSTG) * STAGE_BYTES;
        const uint32_t sB = sa + B_OFF;
#pragma unroll
        for (int ks = 0; ks < 2; ks++) {
            const uint32_t kb = ks * 32;             // 16 halves = 32B
            uint32_t a[4][4];
#pragma unroll
            for (int mf = 0; mf < 4; mf++) {
                uint32_t addr = sa + (wm + mf * 16 + aRowSel) * ASTRIDE + kb + aKByte;
                ldsm4(a[mf][0], a[mf][1], a[mf][2], a[mf][3], addr);
            }
            uint32_t b[4][2];
#pragma unroll
            for (int np = 0; np < 2; np++) {
                uint32_t addr = sB + (wn + np * 16 + bRowSel) * ASTRIDE + kb + bKByte;
                uint32_t r0, r1, r2, r3;
                ldsm4(r0, r1, r2, r3, addr);
                b[np * 2][0] = r0; b[np * 2][1] = r1;
                b[np * 2 + 1][0] = r2; b[np * 2 + 1][1] = r3;
            }
#pragma unroll
            for (int mf = 0; mf < 4; mf++)
#pragma unroll
                for (int nf = 0; nf < 4; nf++)
                    mma16816(acc[mf][nf], a[mf], b[nf]);
        }
        __syncthreads();
    }

    // epilogue: c0,c1 -> (m = base + lane/4, n = 2*(lane%4)+0/1); c2,c3 -> m+8
    const int erow = lane >> 2, ecol = (lane & 3) * 2;
#pragma unroll
    for (int mf = 0; mf < 4; mf++) {
#pragma unroll
        for (int nf = 0; nf < 4; nf++) {
            const int r = m0 + wm + mf * 16 + erow;
            const int c = n0 + wn + nf * 8 + ecol;
            float2 v0 = {acc[mf][nf][0], acc[mf][nf][1]};
            float2 v1 = {acc[mf][nf][2], acc[mf][nf][3]};
            *(float2*)&C[(size_t)r * KK + c]       = v0;
            *(float2*)&C[(size_t)(r + 8) * KK + c] = v1;
            if (sym && bi != bj) {
                C[(size_t)c * KK + r] = v0.x;
                C[(size_t)(c + 1) * KK + r] = v0.y;
                C[(size_t)c * KK + r + 8] = v1.x;
                C[(size_t)(c + 1) * KK + r + 8] = v1.y;
            }
        }
    }
}

// ---------------- initial ||target||^2 ----------------
__global__ __launch_bounds__(256) void norm0_kernel(const float* __restrict__ targets) {
    const int warp = threadIdx.x >> 5, lane = threadIdx.x & 31;
    const int row = blockIdx.x * 8 + warp;
    const float* tp = targets + (size_t)row * DD;
    float s = 0.0f;
#pragma unroll
    for (int c4 = lane; c4 < DD / 4; c4 += 32) {
        float4 v = *(const float4*)(tp + c4 * 4);
        s += v.x * v.x + v.y * v.y + v.z * v.z + v.w * v.w;
    }
#pragma unroll
    for (int off = 16; off; off >>= 1) s += __shfl_xor_sync(0xffffffffu, s, off);
    if (lane == 0) g_norm2[row] = s;
}

// ---------------- fused 8-step pursuit: block per row, score row in smem ----------------
__global__ __launch_bounds__(256) void step_fused(float* __restrict__ idx_out) {
    __shared__ float s[KK];
    __shared__ float rv[8];
    __shared__ int   ri[8];
    __shared__ int   gsel;

    const int tid = threadIdx.x;
    const int row = blockIdx.x;
    const int warp = tid >> 5, lane = tid & 31;

    const float4* sp = (const float4*)(g_scores + (size_t)row * KK);
#pragma unroll
    for (int i = 0; i < 4; i++) ((float4*)s)[tid + 256 * i] = sp[tid + 256 * i];

    float norm2 = 0.0f;
    bool active = true;
    if (tid == 0) norm2 = g_norm2[row];

    for (int step = 0; step < LL; step++) {
        __syncthreads();
        float bv = -3.402823466e38f; int bi = 0;
#pragma unroll
        for (int i = 0; i < 16; i++) {
            int c = tid + 256 * i;
            float v = s[c];
            if (v > bv || (v == bv && c < bi)) { bv = v; bi = c; }
        }
#pragma unroll
        for (int off = 16; off; off >>= 1) {
            float ov = __shfl_xor_sync(0xffffffffu, bv, off);
            int   oi = __shfl_xor_sync(0xffffffffu, bi, off);
            if (ov > bv || (ov == bv && oi < bi)) { bv = ov; bi = oi; }
        }
        if (lane == 0) { rv[warp] = bv; ri[warp] = bi; }
        __syncthreads();
        if (tid == 0) {
            bv = rv[0]; bi = ri[0];
#pragma unroll
            for (int w = 1; w < 8; w++)
                if (rv[w] > bv || (rv[w] == bv && ri[w] < bi)) { bv = rv[w]; bi = ri[w]; }
            const bool act = active && (norm2 >= 1e-6f);   // norm >= 1e-3
            active = act;
            idx_out[(size_t)row * LL + step] = act ? (float)bi : -1.0f;
            if (act) {
                const float d = c_decay[step];
                norm2 = norm2 - 2.0f * d * bv + d * d * g_gram[(size_t)bi * KK + bi];
            }
            gsel = act ? bi : -1;
        }
        __syncthreads();
        const int sel = gsel;
        if (sel >= 0 && step < LL - 1) {
            const float d = c_decay[step];
            const float4* gp = (const float4*)(g_gram + (size_t)sel * KK);
#pragma unroll
            for (int i = 0; i < 4; i++) {
                int c4 = tid + 256 * i;
                float4 g = gp[c4];
                float4 v = ((float4*)s)[c4];
                v.x -= d * g.x; v.y -= d * g.y; v.z -= d * g.z; v.w -= d * g.w;
                ((float4*)s)[c4] = v;
            }
        }
    }
}

// ---------------- final residual (reference subtraction order) ----------------
__global__ __launch_bounds__(256) void resid_kernel(
    const float* __restrict__ targets, const float* __restrict__ codebook,
    const float* __restrict__ idx_in, float* __restrict__ out)
{
    const int warp = threadIdx.x >> 5, lane = threadIdx.x & 31;
    const int row = blockIdx.x * 8 + warp;
    int sidx[LL];
#pragma unroll
    for (int s = 0; s < LL; s++) {
        float pv = idx_in[(size_t)row * LL + s];
        sidx[s] = (pv >= 0.0f) ? (int)pv : -1;
    }
    const float* tp = targets + (size_t)row * DD;
    float* op = out + (size_t)row * DD;
#pragma unroll
    for (int c4 = lane; c4 < DD / 4; c4 += 32) {
        float4 v = *(const float4*)(tp + c4 * 4);
#pragma unroll
        for (int s = 0; s < LL; s++) {
            if (sidx[s] >= 0) {
                const float d = c_decay[s];
                float4 c = *(const float4*)(codebook + (size_t)sidx[s] * DD + c4 * 4);
                v.x -= d * c.x; v.y -= d * c.y; v.z -= d * c.z; v.w -= d * c.w;
            }
        }
        *(float4*)(op + c4 * 4) = v;
    }
}

__global__ void f2i_kernel(const float* __restrict__ src, int* __restrict__ dst, int n) {
    int i = blockIdx.x * blockDim.x + threadIdx.x;
    if (i < n) dst[i] = (int)src[i];
}

// ---------------- host ----------------
extern "C" void kernel_launch(void* const* d_in, const int* in_sizes, int n_in,
                              void* d_out, int out_size)
{
    const float* targets  = (const float*)d_in[0];
    const float* codebook = (const float*)d_in[1];

    void *scoresPtr = nullptr, *gramPtr = nullptr, *scrPtr = nullptr;
    void *taPtr = nullptr, *caPtr = nullptr, *cbPtr = nullptr;
    cudaGetSymbolAddress(&scoresPtr, g_scores);
    cudaGetSymbolAddress(&gramPtr, g_gram);
    cudaGetSymbolAddress(&scrPtr, g_idx_scratch);
    cudaGetSymbolAddress(&taPtr, g_Ta);
    cudaGetSymbolAddress(&caPtr, g_Ca);
    cudaGetSymbolAddress(&cbPtr, g_Cb);

    const int IDX_N = BB * LL, RES_N = BB * DD;
    float* out = (float*)d_out;
    const bool full_layout = (out_size >= IDX_N + RES_N);
    float* idx_out = full_layout ? out : (float*)scrPtr;
    float* res_out = full_layout ? (out + IDX_N)
                   : (out_size == RES_N ? out : (float*)scoresPtr);

    const int SMEM = NSTG * STAGE_BYTES;   // 61440
    static bool attr_done = false;
    if (!attr_done) {
        cudaFuncSetAttribute(gemm_split, cudaFuncAttributeMaxDynamicSharedMemorySize, SMEM);
        attr_done = true;
    }

    // 1) bf16 3-way splits
    split_targets<<<BB * DD / 256, 256>>>(targets);
    split_codebook<<<KK * DD / 256, 256>>>(codebook);

    // 2) scores0 = T @ C^T and G = C @ C^T (sym) via bf16 mma.sync split GEMM
    gemm_split<<<dim3(KK / BN, BB / BB_ROWS), 256, SMEM>>>(
        (const __nv_bfloat16*)taPtr, (const __nv_bfloat16*)cbPtr, (float*)scoresPtr, 0);
    gemm_split<<<dim3(KK / BN, KK / BB_ROWS), 256, SMEM>>>(
        (const __nv_bfloat16*)caPtr, (const __nv_bfloat16*)cbPtr, (float*)gramPtr, 1);

    // 3) norms, fused pursuit, residual
    norm0_kernel<<<BB / 8, 256>>>(targets);
    step_fused<<<BB, 256>>>(idx_out);
    resid_kernel<<<BB / 8, 256>>>(targets, codebook, idx_out, res_out);

    if (!full_layout && out_size == IDX_N) {
        f2i_kernel<<<(IDX_N + 255) / 256, 256>>>((const float*)scrPtr, (int*)d_out, IDX_N);
    }
}